// round 15
// baseline (speedup 1.0000x reference)
#include <cuda_runtime.h>
#include <cuda_bf16.h>
#include <math.h>
#include <stdint.h>

#define NBATCH 256
#define CCH    256
#define VDIM   25
#define TDIM   20
#define C4DIM  64
#define ODIM   256
#define EPSV   1e-5f

// Scratch (no cudaMalloc allowed)
__device__ float g_l     [NBATCH * CCH * TDIM];   // (N, C, T) sigmoid gate
__device__ float g_kern  [NBATCH * CCH * 3];      // (N, C, K) softmax kernel
// W' in HMMA A-fragment layout: [ks(48)][mt(16)][lane(32)] uint4
__device__ uint4 g_Wfrag4[48 * 16 * 32];          // 384 KB

__device__ __forceinline__ uint32_t smem_u32(const void* p) {
    uint32_t a;
    asm("{ .reg .u64 t; cvta.to.shared.u64 t, %1; cvt.u32.u64 %0, t; }" : "=r"(a) : "l"(p));
    return a;
}

// ============================================================
// K0: precompute W' fragments. 3-term bf16 split, slot map per
// channel pair (c=2cp, d=2cp+1):
//   slots 6cp..6cp+5 : A = [Whi_c, Whi_c, Wlo_c, Whi_d, Whi_d, Wlo_d]
//                      B = [mhi_c, mlo_c, mhi_c, mhi_d, mlo_d, mhi_d]
// ============================================================
__global__ void __launch_bounds__(256) k_wprep(const float* __restrict__ Wc2) {
    const int g    = blockIdx.x * 256 + threadIdx.x;   // u32 index, 0..98303
    const int j    = g & 3;
    const int lane = (g >> 2) & 31;
    const int mt   = (g >> 7) & 15;
    const int ks   = g >> 11;
    const int k0   = ks * 16 + (j >> 1) * 8 + (lane & 3) * 2;
    const int o    = mt * 16 + (j & 1) * 8 + (lane >> 2);
    uint32_t pk = 0;
    #pragma unroll
    for (int e = 0; e < 2; e++) {
        int k  = k0 + e;
        int cp = k / 6, r = k - 6 * cp;
        int c  = 2 * cp + (r >= 3 ? 1 : 0);
        int sub = r % 3;                       // 0,1 -> Whi ; 2 -> Wlo
        float w = Wc2[o * 256 + c];
        __nv_bfloat16 hi = __float2bfloat16_rn(w);
        __nv_bfloat16 v  = (sub == 2) ? __float2bfloat16_rn(w - __bfloat162float(hi)) : hi;
        pk |= (uint32_t)__bfloat16_as_ushort(v) << (16 * e);
    }
    ((uint32_t*)g_Wfrag4)[g] = pk;
}

// ============================================================
// K1 (fused): pool over V (cp.async pipelined) + G branch + L branch.
// One block per n (n = nbase + blockIdx.x), 512 threads, dynamic smem.
// ============================================================
#define P_PS    0                           // [256][24] f32 = 24576
#define P_BUF0  24576                       // 16 rows x 129 float4 = 33024
#define P_BUF1  57600                       // 33024
#define P_L1    90624                       // 64x20 f32 = 5120
#define P_WG1   95744                       // 3200
#define P_WG2   98944                       // 480
#define P_AG    99424                       // 160
#define P_BG    99584                       // 160
#define SMEM_PREP 99744

__global__ void __launch_bounds__(512) k_prep(
    const float* __restrict__ x,
    const float* __restrict__ Wg1, const float* __restrict__ Wg2,
    const float* __restrict__ Wl1, const float* __restrict__ Wl2,
    const float* __restrict__ bng, const float* __restrict__ bnl,
    int nbase)
{
    extern __shared__ char smc[];
    float* p_s   = (float*)(smc + P_PS);
    float* buf0  = (float*)(smc + P_BUF0);
    float* buf1  = (float*)(smc + P_BUF1);
    float* l1_s  = (float*)(smc + P_L1);
    float* wg1_s = (float*)(smc + P_WG1);
    float* wg2_s = (float*)(smc + P_WG2);
    float* Ag    = (float*)(smc + P_AG);
    float* Bg    = (float*)(smc + P_BG);

    const int n   = nbase + blockIdx.x;
    const int tid = threadIdx.x;
    const uint32_t sbuf0 = smem_u32(buf0);
    const uint32_t sbuf1 = smem_u32(buf1);

    // small weight loads + p_s padding zeros
    for (int i = tid; i < 800; i += 512) wg1_s[i] = Wg1[i];
    if (tid < 120) wg2_s[tid] = Wg2[tid];
    if (tid < 40) {
        float g = bng[tid], b = bng[40 + tid], m = bng[80 + tid], v = bng[120 + tid];
        float a = g * rsqrtf(v + EPSV);
        Ag[tid] = a;
        Bg[tid] = b - m * a;
    }
    if (tid < 256) {
        p_s[tid * 24 + 0]  = 0.f;
        p_s[tid * 24 + 21] = 0.f;
        p_s[tid * 24 + 22] = 0.f;
        p_s[tid * 24 + 23] = 0.f;
    }

    // ---- pipelined pooling: 16 rounds x 16 rows, cp.async double-buffered ----
    auto poolLoad = [&](int r) {
        const int rowbase = r * 16;
        #pragma unroll
        for (int q = 0; q < 4; q++) {
            const int idx  = q * 512 + tid;      // 0..2047
            const int row  = idx >> 7;           // 0..15
            const int col4 = idx & 127;
            if (col4 < 125) {
                const float* src = x + ((long)n * CCH + rowbase + row) * 500 + col4 * 4;
                uint32_t dst = ((r & 1) ? sbuf1 : sbuf0) + (uint32_t)(row * 129 + col4) * 16;
                asm volatile("cp.async.cg.shared.global [%0], [%1], 16;"
                             :: "r"(dst), "l"(src) : "memory");
            }
        }
        asm volatile("cp.async.commit_group;" ::: "memory");
    };

    poolLoad(0);
    #pragma unroll 1
    for (int r = 0; r < 16; r++) {
        if (r < 15) {
            poolLoad(r + 1);
            asm volatile("cp.async.wait_group 1;" ::: "memory");
        } else {
            asm volatile("cp.async.wait_group 0;" ::: "memory");
        }
        __syncthreads();
        if (tid < 320) {
            const int row = tid / 20, t = tid - row * 20;
            const float* bp = ((r & 1) ? buf1 : buf0) + row * 516 + t;
            float s = 0.f;
            #pragma unroll
            for (int v = 0; v < VDIM; v++) s += bp[v * 20];
            p_s[(r * 16 + row) * 24 + 1 + t] = s * (1.f / VDIM);
        }
        __syncthreads();
    }

    float* part = buf0;   // reuse as part[j][tq8][t]

    {   // ---- L stage 1 partials: all 512 threads, 8-way c split ----
        const int j  = tid >> 3;
        const int tq = tid & 7;
        float acc[TDIM];
        #pragma unroll
        for (int t = 0; t < TDIM; t++) acc[t] = 0.f;
        const float* wl = Wl1 + (long)j * CCH * 3;
        for (int c = tq; c < CCH; c += 8) {
            float w0 = __ldg(wl + c * 3), w1 = __ldg(wl + c * 3 + 1), w2 = __ldg(wl + c * 3 + 2);
            const float* pr = p_s + c * 24;
            #pragma unroll
            for (int t = 0; t < TDIM; t++)
                acc[t] = fmaf(w0, pr[t], fmaf(w1, pr[t + 1], fmaf(w2, pr[t + 2], acc[t])));
        }
        #pragma unroll
        for (int t = 0; t < TDIM; t++) part[(j * 8 + tq) * TDIM + t] = acc[t];
    }
    __syncthreads();

    if (tid < 256) {
        // ---- stage 1 reduce + bn + relu ----
        const int j  = tid >> 2;
        const int tq = tid & 3;
        float g = bnl[j], b = bnl[64 + j], m = bnl[128 + j], v = bnl[192 + j];
        float a  = g * rsqrtf(v + EPSV);
        float bb = b - m * a;
        #pragma unroll
        for (int u = 0; u < 5; u++) {
            int t = tq * 5 + u;
            float s = 0.f;
            #pragma unroll
            for (int q = 0; q < 8; q++) s += part[(j * 8 + q) * TDIM + t];
            l1_s[j * TDIM + t] = fmaxf(fmaf(a, s, bb), 0.f);
        }
    } else {
        // ---- G branch (threads 256..511), c = tid-256 ----
        const int c = tid - 256;
        float pr[TDIM];
        #pragma unroll
        for (int t = 0; t < TDIM; t++) pr[t] = p_s[c * 24 + 1 + t];
        float h[40];
        #pragma unroll
        for (int i = 0; i < 40; i++) {
            float s = 0.f;
            #pragma unroll
            for (int t = 0; t < TDIM; t++)
                s = fmaf(wg1_s[i * TDIM + t], pr[t], s);
            h[i] = fmaxf(fmaf(Ag[i], s, Bg[i]), 0.f);
        }
        float z0 = 0.f, z1 = 0.f, z2 = 0.f;
        #pragma unroll
        for (int i = 0; i < 40; i++) {
            z0 = fmaf(wg2_s[i],      h[i], z0);
            z1 = fmaf(wg2_s[40 + i], h[i], z1);
            z2 = fmaf(wg2_s[80 + i], h[i], z2);
        }
        float mx = fmaxf(z0, fmaxf(z1, z2));
        float e0 = expf(z0 - mx), e1 = expf(z1 - mx), e2 = expf(z2 - mx);
        float inv = 1.f / (e0 + e1 + e2);
        long kb = ((long)n * CCH + c) * 3;
        g_kern[kb + 0] = e0 * inv;
        g_kern[kb + 1] = e1 * inv;
        g_kern[kb + 2] = e2 * inv;
    }
    __syncthreads();

    if (tid < 256) {   // ---- L stage 2: l[c,t] = sigmoid(Wl2 @ l1) ----
        const int c = tid;
        float acc[TDIM];
        #pragma unroll
        for (int t = 0; t < TDIM; t++) acc[t] = 0.f;
        const float4* w4 = (const float4*)(Wl2 + c * C4DIM);
        #pragma unroll 4
        for (int q = 0; q < C4DIM / 4; q++) {
            float4 wv = __ldg(&w4[q]);
            #pragma unroll
            for (int t = 0; t < TDIM; t++) {
                acc[t] = fmaf(wv.x, l1_s[(4 * q + 0) * TDIM + t], acc[t]);
                acc[t] = fmaf(wv.y, l1_s[(4 * q + 1) * TDIM + t], acc[t]);
                acc[t] = fmaf(wv.z, l1_s[(4 * q + 2) * TDIM + t], acc[t]);
                acc[t] = fmaf(wv.w, l1_s[(4 * q + 3) * TDIM + t], acc[t]);
            }
        }
        float* lo = g_l + ((long)n * CCH + c) * TDIM;
        #pragma unroll
        for (int t = 0; t < TDIM; t++)
            lo[t] = 1.f / (1.f + expf(-acc[t]));
    }
}

// ============================================================
// K3: HMMA main (best-known config). Block = 256 thr (8 warps, 4Mx2N),
//   2 blocks/SM. Tile = FULL M=256 o x 64 pos, grid (8 postiles, nchunk).
//   K=768 in 16 stages of 3 ks. A cp.async double-buffered; B built once.
// ============================================================
#define A_STG 24576                         // 3ks x 16mt x 32lane x 16B
#define B_STG 6144                          // 3plg x 8pg x 32lane x 8B
#define OFF_A0    0
#define OFF_A1    A_STG
#define OFF_B0    (2 * A_STG)               // 49152
#define OFF_B1    (OFF_B0 + B_STG)          // 55296
#define OFF_SL    (OFF_B1 + B_STG)          // 61440
#define OFF_SK    (OFF_SL + 256 * 20 * 4)   // 81920
#define OFF_SAB   (OFF_SK + 256 * 3 * 4)    // 84992
#define OFF_SAB2  (OFF_SAB + 2048)          // 87040
#define SMEM_TOT  (OFF_SAB2 + 2048)         // 89088

__device__ __forceinline__ void mma16816(float* d, const uint32_t* a, const uint32_t* b) {
    asm volatile(
        "mma.sync.aligned.m16n8k16.row.col.f32.bf16.bf16.f32 "
        "{%0,%1,%2,%3}, {%4,%5,%6,%7}, {%8,%9}, {%0,%1,%2,%3};"
        : "+f"(d[0]), "+f"(d[1]), "+f"(d[2]), "+f"(d[3])
        : "r"(a[0]), "r"(a[1]), "r"(a[2]), "r"(a[3]), "r"(b[0]), "r"(b[1]));
}

__global__ void __launch_bounds__(256, 2) k_main_mma(
    const float* __restrict__ x,
    const float* __restrict__ bn1p, const float* __restrict__ bn2p,
    float* __restrict__ out, int nbase)
{
    extern __shared__ char sm[];
    float* sl   = (float*)(sm + OFF_SL);
    float* sk   = (float*)(sm + OFF_SK);
    float* sab  = (float*)(sm + OFF_SAB);
    float* sab2 = (float*)(sm + OFF_SAB2);

    const int tid = threadIdx.x, wid = tid >> 5, lid = tid & 31;
    const int n = nbase + blockIdx.y;
    const int posbase = blockIdx.x * 64;
    const int warpM = wid >> 1, warpN = wid & 1;   // 4M x 2N
    const uint32_t sbase = smem_u32(sm);

    // per-thread position geometry (lane = 2 contiguous pos)
    const int pos0 = posbase + lid * 2;
    const bool pv  = pos0 < 500;
    const int t0   = pos0 % 20;                    // even

    // ---- per-c / per-o prep ----
    {
        const int c = tid;
        const float* lr = g_l + ((long)n * CCH + c) * TDIM;
        #pragma unroll
        for (int t = 0; t < TDIM; t++) sl[c * 20 + t] = lr[t];
        long kb = ((long)n * CCH + c) * 3;
        sk[c * 3 + 0] = g_kern[kb + 0];
        sk[c * 3 + 1] = g_kern[kb + 1];
        sk[c * 3 + 2] = g_kern[kb + 2];
        float g = bn1p[c], be = bn1p[256 + c], mu = bn1p[512 + c], va = bn1p[768 + c];
        float a1 = g * rsqrtf(va + EPSV);
        sab[2 * c] = a1;
        sab[2 * c + 1] = be - mu * a1;
        g = bn2p[c]; be = bn2p[256 + c]; mu = bn2p[512 + c]; va = bn2p[768 + c];
        float a2 = g * rsqrtf(va + EPSV);
        sab2[2 * c] = a2;
        sab2[2 * c + 1] = be - mu * a2;
    }
    __syncthreads();

    // ---- cp.async one A stage (24KB = 6 chunks of 16B per thread) ----
    auto stageA = [&](int s, int abuf) {
        uint32_t dst = sbase + abuf * A_STG + (uint32_t)tid * 16;
        const uint4* src = g_Wfrag4 + s * 1536 + tid;
        #pragma unroll
        for (int k = 0; k < 6; k++)
            asm volatile("cp.async.cg.shared.global [%0], [%1], 16;"
                         :: "r"(dst + k * 4096), "l"(src + k * 256) : "memory");
        asm volatile("cp.async.commit_group;" ::: "memory");
    };

    // ---- B build, load half: x LDGs for stage s (warp = 1 channel pair) ----
    float xr[2][4];
    auto bload = [&](int s) {
        #pragma unroll
        for (int e = 0; e < 2; e++) {
            const int ch = 16 * s + wid * 2 + e;
            const float* xrow = x + ((long)n * CCH + ch) * 500;
            if (pv) {
                float2 v2 = *(const float2*)(xrow + pos0);
                xr[e][1] = v2.x; xr[e][2] = v2.y;
                xr[e][0] = (t0 != 0)      ? xrow[pos0 - 1] : 0.f;
                xr[e][3] = (t0 + 1 != 19) ? xrow[pos0 + 2] : 0.f;
            } else {
                xr[e][0] = xr[e][1] = xr[e][2] = xr[e][3] = 0.f;
            }
        }
    };

    // ---- B build, store half: conv+bn1+relu+split+pack+swizzled STS ----
    auto bstore = [&](int s, uint32_t* buf) {
        float mv[2][2];
        #pragma unroll
        for (int e = 0; e < 2; e++) {
            const int ch = 16 * s + wid * 2 + e;
            const float k0 = sk[ch * 3], k1 = sk[ch * 3 + 1], k2 = sk[ch * 3 + 2];
            const float a1 = sab[2 * ch], b1 = sab[2 * ch + 1];
            const float* lrow = sl + ch * 20;
            int t = t0;
            #pragma unroll
            for (int j = 0; j < 2; j++) {
                float s_  = xr[e][j + 1] + lrow[t];
                float smv = (t == 0)  ? 0.f : xr[e][j]     + lrow[t - 1];
                float spv = (t == 19) ? 0.f : xr[e][j + 2] + lrow[t + 1];
                float m = k0 * smv + k1 * s_ + k2 * spv;
                mv[e][j] = pv ? fmaxf(fmaf(a1, m, b1), 0.f) : 0.f;
                t++;
            }
        }
        const int pl0 = 3 * wid;               // pair-local u32-pair base (0..21)
        #pragma unroll
        for (int j = 0; j < 2; j++) {
            __nv_bfloat16 h0b = __float2bfloat16_rn(mv[0][j]);
            __nv_bfloat16 l0b = __float2bfloat16_rn(mv[0][j] - __bfloat162float(h0b));
            __nv_bfloat16 h1b = __float2bfloat16_rn(mv[1][j]);
            __nv_bfloat16 l1b = __float2bfloat16_rn(mv[1][j] - __bfloat162float(h1b));
            uint32_t h0 = __bfloat16_as_ushort(h0b), lo0 = __bfloat16_as_ushort(l0b);
            uint32_t h1 = __bfloat16_as_ushort(h1b), lo1 = __bfloat16_as_ushort(l1b);
            uint32_t u0 = h0  | (lo0 << 16);    // (mhi_c, mlo_c)
            uint32_t u1 = h0  | (h1  << 16);    // (mhi_c, mhi_d)
            uint32_t u2 = lo1 | (h1  << 16);    // (mlo_d, mhi_d)
            const int posl = lid * 2 + j;
            const int pg = posl >> 3, ii = posl & 7;
            #pragma unroll
            for (int q = 0; q < 3; q++) {
                const int pl   = pl0 + q;
                const int phys = (ii * 4 + (pl & 3)) ^ pg;   // XOR swizzle
                const int idx  = ((((pl >> 3) * 8 + pg) * 32 + phys) << 1)
                                 + ((pl >> 2) & 1);
                buf[idx] = (q == 0) ? u0 : (q == 1) ? u1 : u2;
            }
        }
    };

    // ---- prologue ----
    stageA(0, 0);
    bload(0);
    bstore(0, (uint32_t*)(sm + OFF_B0));
    bload(1);
    asm volatile("cp.async.wait_group 0;" ::: "memory");
    __syncthreads();

    float acc[4][4][4];
    #pragma unroll
    for (int m = 0; m < 4; m++)
        #pragma unroll
        for (int q = 0; q < 4; q++)
            #pragma unroll
            for (int r = 0; r < 4; r++) acc[m][q][r] = 0.f;

    // ---- pipelined mainloop: 16 stages of 3 ks ----
    #pragma unroll 1
    for (int s = 0; s < 16; s++) {
        if (s < 15) stageA(s + 1, (s + 1) & 1);

        const char* smA = sm + (s & 1) * A_STG;
        const char* smB = sm + ((s & 1) ? OFF_B1 : OFF_B0);

        #pragma unroll 1
        for (int ks = 0; ks < 3; ks++) {
            uint32_t a[4][4];
            #pragma unroll
            for (int mt = 0; mt < 4; mt++) {
                uint4 v = *(const uint4*)(smA + (((ks * 16) + warpM * 4 + mt) * 32 + lid) * 16);
                a[mt][0] = v.x; a[mt][1] = v.y; a[mt][2] = v.z; a[mt][3] = v.w;
            }
            uint32_t b[4][2];
            #pragma unroll
            for (int nt = 0; nt < 4; nt++) {
                const int pgrp = warpN * 4 + nt;
                uint2 v = *(const uint2*)(smB + (((ks * 8) + pgrp) * 32 + (lid ^ pgrp)) * 8);
                b[nt][0] = v.x; b[nt][1] = v.y;
            }
            #pragma unroll
            for (int mt = 0; mt < 4; mt++)
                #pragma unroll
                for (int nt = 0; nt < 4; nt++)
                    mma16816(acc[mt][nt], a[mt], b[nt]);
        }

        if (s < 15) bstore(s + 1, (uint32_t*)(sm + ((s & 1) ? OFF_B0 : OFF_B1)));
        if (s < 14) bload(s + 2);

        if (s < 15) {
            asm volatile("cp.async.wait_group 0;" ::: "memory");  // A(s+1) landed
            __syncthreads();
        }
    }

    // ---- epilogue: bn2 + relu, direct STG.64 ----
    #pragma unroll
    for (int mt = 0; mt < 4; mt++) {
        const int o0 = warpM * 64 + mt * 16 + (lid >> 2);
        const float a20 = sab2[2 * o0],       b20 = sab2[2 * o0 + 1];
        const float a21 = sab2[2 * (o0 + 8)], b21 = sab2[2 * (o0 + 8) + 1];
        float* orow0 = out + ((long)n * 256 + o0) * 500;
        float* orow1 = orow0 + 8 * 500;
        #pragma unroll
        for (int nt = 0; nt < 4; nt++) {
            const int pos = posbase + warpN * 32 + nt * 8 + (lid & 3) * 2;
            if (pos < 500) {
                float2 v0, v1;
                v0.x = fmaxf(fmaf(a20, acc[mt][nt][0], b20), 0.f);
                v0.y = fmaxf(fmaf(a20, acc[mt][nt][1], b20), 0.f);
                v1.x = fmaxf(fmaf(a21, acc[mt][nt][2], b21), 0.f);
                v1.y = fmaxf(fmaf(a21, acc[mt][nt][3], b21), 0.f);
                *(float2*)(orow0 + pos) = v0;
                *(float2*)(orow1 + pos) = v1;
            }
        }
    }
}

// ============================================================
// Launch: fork prep onto a side stream; main waits per-chunk.
//   s0: wprep ─ wait(ev0) ─ main(0..127) ─ wait(ev1) ─ main(128..255)
//   s1: prep(0..127)→ev0 ─ prep(128..255)→ev1
// ============================================================
#define NCHUNK 2
#define CHUNKN (NBATCH / NCHUNK)

extern "C" void kernel_launch(void* const* d_in, const int* in_sizes, int n_in,
                              void* d_out, int out_size) {
    const float* x    = (const float*)d_in[0];
    const float* Wg1  = (const float*)d_in[1];
    const float* Wg2  = (const float*)d_in[2];
    const float* Wl1  = (const float*)d_in[3];
    const float* Wl2  = (const float*)d_in[4];
    const float* Wc2  = (const float*)d_in[5];
    const float* bng  = (const float*)d_in[6];
    const float* bnl  = (const float*)d_in[7];
    const float* bn1p = (const float*)d_in[8];
    const float* bn2p = (const float*)d_in[9];
    float* out = (float*)d_out;

    static cudaStream_t s1 = nullptr;
    static cudaEvent_t evFork, evPrep[NCHUNK];
    if (!s1) {
        cudaFuncSetAttribute(k_main_mma, cudaFuncAttributeMaxDynamicSharedMemorySize, SMEM_TOT);
        cudaFuncSetAttribute(k_prep, cudaFuncAttributeMaxDynamicSharedMemorySize, SMEM_PREP);
        cudaStreamCreateWithFlags(&s1, cudaStreamNonBlocking);
        cudaEventCreateWithFlags(&evFork, cudaEventDisableTiming);
        for (int h = 0; h < NCHUNK; h++)
            cudaEventCreateWithFlags(&evPrep[h], cudaEventDisableTiming);
    }

    // fork side stream off the launch stream
    cudaEventRecord(evFork, 0);
    cudaStreamWaitEvent(s1, evFork, 0);

    // prep chunks on side stream
    for (int h = 0; h < NCHUNK; h++) {
        k_prep<<<CHUNKN, 512, SMEM_PREP, s1>>>(x, Wg1, Wg2, Wl1, Wl2, bng, bnl, h * CHUNKN);
        cudaEventRecord(evPrep[h], s1);
    }

    // main stream: W prep overlaps with prep chunk 0
    k_wprep<<<384, 256>>>(Wc2);
    for (int h = 0; h < NCHUNK; h++) {
        cudaStreamWaitEvent(0, evPrep[h], 0);
        k_main_mma<<<dim3(8, CHUNKN), 256, SMEM_TOT>>>(x, bn1p, bn2p, out, h * CHUNKN);
    }
}

// round 17
// speedup vs baseline: 1.0481x; 1.0481x over previous
#include <cuda_runtime.h>
#include <cuda_bf16.h>
#include <math.h>
#include <stdint.h>

#define NBATCH 256
#define CCH    256
#define VDIM   25
#define TDIM   20
#define C4DIM  64
#define ODIM   256
#define EPSV   1e-5f

// Scratch (no cudaMalloc allowed)
__device__ float g_l     [NBATCH * CCH * TDIM];   // (N, C, T) sigmoid gate
__device__ float g_kern  [NBATCH * CCH * 3];      // (N, C, K) softmax kernel
// W' in HMMA A-fragment layout: [ks(48)][mt(16)][lane(32)] uint4
__device__ uint4 g_Wfrag4[48 * 16 * 32];          // 384 KB

__device__ __forceinline__ uint32_t smem_u32(const void* p) {
    uint32_t a;
    asm("{ .reg .u64 t; cvta.to.shared.u64 t, %1; cvt.u32.u64 %0, t; }" : "=r"(a) : "l"(p));
    return a;
}

// ============================================================
// K0: precompute W' fragments. 3-term bf16 split, slot map per
// channel pair (c=2cp, d=2cp+1):
//   slots 6cp..6cp+5 : A = [Whi_c, Whi_c, Wlo_c, Whi_d, Whi_d, Wlo_d]
//                      B = [mhi_c, mlo_c, mhi_c, mhi_d, mlo_d, mhi_d]
// ============================================================
__global__ void __launch_bounds__(256) k_wprep(const float* __restrict__ Wc2) {
    const int g    = blockIdx.x * 256 + threadIdx.x;   // u32 index, 0..98303
    const int j    = g & 3;
    const int lane = (g >> 2) & 31;
    const int mt   = (g >> 7) & 15;
    const int ks   = g >> 11;
    const int k0   = ks * 16 + (j >> 1) * 8 + (lane & 3) * 2;
    const int o    = mt * 16 + (j & 1) * 8 + (lane >> 2);
    uint32_t pk = 0;
    #pragma unroll
    for (int e = 0; e < 2; e++) {
        int k  = k0 + e;
        int cp = k / 6, r = k - 6 * cp;
        int c  = 2 * cp + (r >= 3 ? 1 : 0);
        int sub = r % 3;                       // 0,1 -> Whi ; 2 -> Wlo
        float w = Wc2[o * 256 + c];
        __nv_bfloat16 hi = __float2bfloat16_rn(w);
        __nv_bfloat16 v  = (sub == 2) ? __float2bfloat16_rn(w - __bfloat162float(hi)) : hi;
        pk |= (uint32_t)__bfloat16_as_ushort(v) << (16 * e);
    }
    ((uint32_t*)g_Wfrag4)[g] = pk;
}

// ============================================================
// K1 (fused): pool over V (cp.async pipelined) + G branch + L branch.
// One block per n, 512 threads, dynamic smem.
// p_s row stride = 25 floats (odd) -> conflict-free for both the
// stage-1 pattern (c = tq + 8k) and the G-branch pattern (c = lane).
// ============================================================
#define PSTR    25
#define P_PS    0                           // [256][25] f32 = 25600
#define P_BUF0  25600                       // 16 rows x 129 float4 = 33024
#define P_BUF1  58624                       // 33024
#define P_L1    91648                       // 64x20 f32 = 5120
#define P_WG1   96768                       // 3200
#define P_WG2   99968                       // 480
#define P_AG    100448                      // 160
#define P_BG    100608                      // 160
#define SMEM_PREP 100768

__global__ void __launch_bounds__(512) k_prep(
    const float* __restrict__ x,
    const float* __restrict__ Wg1, const float* __restrict__ Wg2,
    const float* __restrict__ Wl1, const float* __restrict__ Wl2,
    const float* __restrict__ bng, const float* __restrict__ bnl)
{
    extern __shared__ char smc[];
    float* p_s   = (float*)(smc + P_PS);
    float* buf0  = (float*)(smc + P_BUF0);
    float* buf1  = (float*)(smc + P_BUF1);
    float* l1_s  = (float*)(smc + P_L1);
    float* wg1_s = (float*)(smc + P_WG1);
    float* wg2_s = (float*)(smc + P_WG2);
    float* Ag    = (float*)(smc + P_AG);
    float* Bg    = (float*)(smc + P_BG);

    const int n   = blockIdx.x;
    const int tid = threadIdx.x;
    const uint32_t sbuf0 = smem_u32(buf0);
    const uint32_t sbuf1 = smem_u32(buf1);

    // small weight loads + p_s padding zeros
    for (int i = tid; i < 800; i += 512) wg1_s[i] = Wg1[i];
    if (tid < 120) wg2_s[tid] = Wg2[tid];
    if (tid < 40) {
        float g = bng[tid], b = bng[40 + tid], m = bng[80 + tid], v = bng[120 + tid];
        float a = g * rsqrtf(v + EPSV);
        Ag[tid] = a;
        Bg[tid] = b - m * a;
    }
    if (tid < 256) {
        p_s[tid * PSTR + 0]  = 0.f;        // left pad
        p_s[tid * PSTR + 21] = 0.f;        // right pad
    }

    // ---- pipelined pooling: 16 rounds x 16 rows, cp.async double-buffered ----
    auto poolLoad = [&](int r) {
        const int rowbase = r * 16;
        #pragma unroll
        for (int q = 0; q < 4; q++) {
            const int idx  = q * 512 + tid;      // 0..2047
            const int row  = idx >> 7;           // 0..15
            const int col4 = idx & 127;
            if (col4 < 125) {
                const float* src = x + ((long)n * CCH + rowbase + row) * 500 + col4 * 4;
                uint32_t dst = ((r & 1) ? sbuf1 : sbuf0) + (uint32_t)(row * 129 + col4) * 16;
                asm volatile("cp.async.cg.shared.global [%0], [%1], 16;"
                             :: "r"(dst), "l"(src) : "memory");
            }
        }
        asm volatile("cp.async.commit_group;" ::: "memory");
    };

    poolLoad(0);
    #pragma unroll 1
    for (int r = 0; r < 16; r++) {
        if (r < 15) {
            poolLoad(r + 1);
            asm volatile("cp.async.wait_group 1;" ::: "memory");
        } else {
            asm volatile("cp.async.wait_group 0;" ::: "memory");
        }
        __syncthreads();
        if (tid < 320) {
            const int row = tid / 20, t = tid - row * 20;
            const float* bp = ((r & 1) ? buf1 : buf0) + row * 516 + t;
            float s = 0.f;
            #pragma unroll
            for (int v = 0; v < VDIM; v++) s += bp[v * 20];
            p_s[(r * 16 + row) * PSTR + 1 + t] = s * (1.f / VDIM);
        }
        __syncthreads();
    }

    float* part = buf0;   // reuse as part[j][tq8][t]

    {   // ---- L stage 1 partials: all 512 threads, 8-way c split ----
        const int j  = tid >> 3;
        const int tq = tid & 7;
        float acc[TDIM];
        #pragma unroll
        for (int t = 0; t < TDIM; t++) acc[t] = 0.f;
        const float* wl = Wl1 + (long)j * CCH * 3;
        for (int c = tq; c < CCH; c += 8) {
            float w0 = __ldg(wl + c * 3), w1 = __ldg(wl + c * 3 + 1), w2 = __ldg(wl + c * 3 + 2);
            const float* pr = p_s + c * PSTR;
            #pragma unroll
            for (int t = 0; t < TDIM; t++)
                acc[t] = fmaf(w0, pr[t], fmaf(w1, pr[t + 1], fmaf(w2, pr[t + 2], acc[t])));
        }
        #pragma unroll
        for (int t = 0; t < TDIM; t++) part[(j * 8 + tq) * TDIM + t] = acc[t];
    }
    __syncthreads();

    if (tid < 256) {
        // ---- stage 1 reduce + bn + relu ----
        const int j  = tid >> 2;
        const int tq = tid & 3;
        float g = bnl[j], b = bnl[64 + j], m = bnl[128 + j], v = bnl[192 + j];
        float a  = g * rsqrtf(v + EPSV);
        float bb = b - m * a;
        #pragma unroll
        for (int u = 0; u < 5; u++) {
            int t = tq * 5 + u;
            float s = 0.f;
            #pragma unroll
            for (int q = 0; q < 8; q++) s += part[(j * 8 + q) * TDIM + t];
            l1_s[j * TDIM + t] = fmaxf(fmaf(a, s, bb), 0.f);
        }
    } else {
        // ---- G branch (threads 256..511), c = tid-256 ----
        const int c = tid - 256;
        float pr[TDIM];
        #pragma unroll
        for (int t = 0; t < TDIM; t++) pr[t] = p_s[c * PSTR + 1 + t];
        float h[40];
        #pragma unroll
        for (int i = 0; i < 40; i++) {
            float s = 0.f;
            #pragma unroll
            for (int t = 0; t < TDIM; t++)
                s = fmaf(wg1_s[i * TDIM + t], pr[t], s);
            h[i] = fmaxf(fmaf(Ag[i], s, Bg[i]), 0.f);
        }
        float z0 = 0.f, z1 = 0.f, z2 = 0.f;
        #pragma unroll
        for (int i = 0; i < 40; i++) {
            z0 = fmaf(wg2_s[i],      h[i], z0);
            z1 = fmaf(wg2_s[40 + i], h[i], z1);
            z2 = fmaf(wg2_s[80 + i], h[i], z2);
        }
        float mx = fmaxf(z0, fmaxf(z1, z2));
        float e0 = expf(z0 - mx), e1 = expf(z1 - mx), e2 = expf(z2 - mx);
        float inv = 1.f / (e0 + e1 + e2);
        long kb = ((long)n * CCH + c) * 3;
        g_kern[kb + 0] = e0 * inv;
        g_kern[kb + 1] = e1 * inv;
        g_kern[kb + 2] = e2 * inv;
    }
    __syncthreads();

    if (tid < 256) {   // ---- L stage 2: l[c,t] = sigmoid(Wl2 @ l1) ----
        const int c = tid;
        float acc[TDIM];
        #pragma unroll
        for (int t = 0; t < TDIM; t++) acc[t] = 0.f;
        const float4* w4 = (const float4*)(Wl2 + c * C4DIM);
        #pragma unroll 4
        for (int q = 0; q < C4DIM / 4; q++) {
            float4 wv = __ldg(&w4[q]);
            #pragma unroll
            for (int t = 0; t < TDIM; t++) {
                acc[t] = fmaf(wv.x, l1_s[(4 * q + 0) * TDIM + t], acc[t]);
                acc[t] = fmaf(wv.y, l1_s[(4 * q + 1) * TDIM + t], acc[t]);
                acc[t] = fmaf(wv.z, l1_s[(4 * q + 2) * TDIM + t], acc[t]);
                acc[t] = fmaf(wv.w, l1_s[(4 * q + 3) * TDIM + t], acc[t]);
            }
        }
        float* lo = g_l + ((long)n * CCH + c) * TDIM;
        #pragma unroll
        for (int t = 0; t < TDIM; t++)
            lo[t] = 1.f / (1.f + expf(-acc[t]));
    }
}

// ============================================================
// K3: HMMA main (best-known config). Block = 256 thr (8 warps, 4Mx2N),
//   2 blocks/SM. Tile = FULL M=256 o x 64 pos, grid (8 postiles, n).
//   K=768 in 16 stages of 3 ks. A cp.async double-buffered; B built once.
// ============================================================
#define A_STG 24576                         // 3ks x 16mt x 32lane x 16B
#define B_STG 6144                          // 3plg x 8pg x 32lane x 8B
#define OFF_A0    0
#define OFF_A1    A_STG
#define OFF_B0    (2 * A_STG)               // 49152
#define OFF_B1    (OFF_B0 + B_STG)          // 55296
#define OFF_SL    (OFF_B1 + B_STG)          // 61440
#define OFF_SK    (OFF_SL + 256 * 20 * 4)   // 81920
#define OFF_SAB   (OFF_SK + 256 * 3 * 4)    // 84992
#define OFF_SAB2  (OFF_SAB + 2048)          // 87040
#define SMEM_TOT  (OFF_SAB2 + 2048)         // 89088

__device__ __forceinline__ void mma16816(float* d, const uint32_t* a, const uint32_t* b) {
    asm volatile(
        "mma.sync.aligned.m16n8k16.row.col.f32.bf16.bf16.f32 "
        "{%0,%1,%2,%3}, {%4,%5,%6,%7}, {%8,%9}, {%0,%1,%2,%3};"
        : "+f"(d[0]), "+f"(d[1]), "+f"(d[2]), "+f"(d[3])
        : "r"(a[0]), "r"(a[1]), "r"(a[2]), "r"(a[3]), "r"(b[0]), "r"(b[1]));
}

__global__ void __launch_bounds__(256, 2) k_main_mma(
    const float* __restrict__ x,
    const float* __restrict__ bn1p, const float* __restrict__ bn2p,
    float* __restrict__ out)
{
    extern __shared__ char sm[];
    float* sl   = (float*)(sm + OFF_SL);
    float* sk   = (float*)(sm + OFF_SK);
    float* sab  = (float*)(sm + OFF_SAB);
    float* sab2 = (float*)(sm + OFF_SAB2);

    const int tid = threadIdx.x, wid = tid >> 5, lid = tid & 31;
    const int n = blockIdx.y;
    const int posbase = blockIdx.x * 64;
    const int warpM = wid >> 1, warpN = wid & 1;   // 4M x 2N
    const uint32_t sbase = smem_u32(sm);

    // per-thread position geometry (lane = 2 contiguous pos)
    const int pos0 = posbase + lid * 2;
    const bool pv  = pos0 < 500;
    const int t0   = pos0 % 20;                    // even

    // ---- per-c / per-o prep ----
    {
        const int c = tid;
        const float* lr = g_l + ((long)n * CCH + c) * TDIM;
        #pragma unroll
        for (int t = 0; t < TDIM; t++) sl[c * 20 + t] = lr[t];
        long kb = ((long)n * CCH + c) * 3;
        sk[c * 3 + 0] = g_kern[kb + 0];
        sk[c * 3 + 1] = g_kern[kb + 1];
        sk[c * 3 + 2] = g_kern[kb + 2];
        float g = bn1p[c], be = bn1p[256 + c], mu = bn1p[512 + c], va = bn1p[768 + c];
        float a1 = g * rsqrtf(va + EPSV);
        sab[2 * c] = a1;
        sab[2 * c + 1] = be - mu * a1;
        g = bn2p[c]; be = bn2p[256 + c]; mu = bn2p[512 + c]; va = bn2p[768 + c];
        float a2 = g * rsqrtf(va + EPSV);
        sab2[2 * c] = a2;
        sab2[2 * c + 1] = be - mu * a2;
    }
    __syncthreads();

    // ---- cp.async one A stage (24KB = 6 chunks of 16B per thread) ----
    auto stageA = [&](int s, int abuf) {
        uint32_t dst = sbase + abuf * A_STG + (uint32_t)tid * 16;
        const uint4* src = g_Wfrag4 + s * 1536 + tid;
        #pragma unroll
        for (int k = 0; k < 6; k++)
            asm volatile("cp.async.cg.shared.global [%0], [%1], 16;"
                         :: "r"(dst + k * 4096), "l"(src + k * 256) : "memory");
        asm volatile("cp.async.commit_group;" ::: "memory");
    };

    // ---- B build, load half: x LDGs for stage s (warp = 1 channel pair) ----
    float xr[2][4];
    auto bload = [&](int s) {
        #pragma unroll
        for (int e = 0; e < 2; e++) {
            const int ch = 16 * s + wid * 2 + e;
            const float* xrow = x + ((long)n * CCH + ch) * 500;
            if (pv) {
                float2 v2 = *(const float2*)(xrow + pos0);
                xr[e][1] = v2.x; xr[e][2] = v2.y;
                xr[e][0] = (t0 != 0)      ? xrow[pos0 - 1] : 0.f;
                xr[e][3] = (t0 + 1 != 19) ? xrow[pos0 + 2] : 0.f;
            } else {
                xr[e][0] = xr[e][1] = xr[e][2] = xr[e][3] = 0.f;
            }
        }
    };

    // ---- B build, store half: conv+bn1+relu+split+pack+swizzled STS ----
    auto bstore = [&](int s, uint32_t* buf) {
        float mv[2][2];
        #pragma unroll
        for (int e = 0; e < 2; e++) {
            const int ch = 16 * s + wid * 2 + e;
            const float k0 = sk[ch * 3], k1 = sk[ch * 3 + 1], k2 = sk[ch * 3 + 2];
            const float a1 = sab[2 * ch], b1 = sab[2 * ch + 1];
            const float* lrow = sl + ch * 20;
            int t = t0;
            #pragma unroll
            for (int j = 0; j < 2; j++) {
                float s_  = xr[e][j + 1] + lrow[t];
                float smv = (t == 0)  ? 0.f : xr[e][j]     + lrow[t - 1];
                float spv = (t == 19) ? 0.f : xr[e][j + 2] + lrow[t + 1];
                float m = k0 * smv + k1 * s_ + k2 * spv;
                mv[e][j] = pv ? fmaxf(fmaf(a1, m, b1), 0.f) : 0.f;
                t++;
            }
        }
        const int pl0 = 3 * wid;               // pair-local u32-pair base (0..21)
        #pragma unroll
        for (int j = 0; j < 2; j++) {
            __nv_bfloat16 h0b = __float2bfloat16_rn(mv[0][j]);
            __nv_bfloat16 l0b = __float2bfloat16_rn(mv[0][j] - __bfloat162float(h0b));
            __nv_bfloat16 h1b = __float2bfloat16_rn(mv[1][j]);
            __nv_bfloat16 l1b = __float2bfloat16_rn(mv[1][j] - __bfloat162float(h1b));
            uint32_t h0 = __bfloat16_as_ushort(h0b), lo0 = __bfloat16_as_ushort(l0b);
            uint32_t h1 = __bfloat16_as_ushort(h1b), lo1 = __bfloat16_as_ushort(l1b);
            uint32_t u0 = h0  | (lo0 << 16);    // (mhi_c, mlo_c)
            uint32_t u1 = h0  | (h1  << 16);    // (mhi_c, mhi_d)
            uint32_t u2 = lo1 | (h1  << 16);    // (mlo_d, mhi_d)
            const int posl = lid * 2 + j;
            const int pg = posl >> 3, ii = posl & 7;
            #pragma unroll
            for (int q = 0; q < 3; q++) {
                const int pl   = pl0 + q;
                const int phys = (ii * 4 + (pl & 3)) ^ pg;   // XOR swizzle
                const int idx  = ((((pl >> 3) * 8 + pg) * 32 + phys) << 1)
                                 + ((pl >> 2) & 1);
                buf[idx] = (q == 0) ? u0 : (q == 1) ? u1 : u2;
            }
        }
    };

    // ---- prologue ----
    stageA(0, 0);
    bload(0);
    bstore(0, (uint32_t*)(sm + OFF_B0));
    bload(1);
    asm volatile("cp.async.wait_group 0;" ::: "memory");
    __syncthreads();

    float acc[4][4][4];
    #pragma unroll
    for (int m = 0; m < 4; m++)
        #pragma unroll
        for (int q = 0; q < 4; q++)
            #pragma unroll
            for (int r = 0; r < 4; r++) acc[m][q][r] = 0.f;

    // ---- pipelined mainloop: 16 stages of 3 ks ----
    #pragma unroll 1
    for (int s = 0; s < 16; s++) {
        if (s < 15) stageA(s + 1, (s + 1) & 1);

        const char* smA = sm + (s & 1) * A_STG;
        const char* smB = sm + ((s & 1) ? OFF_B1 : OFF_B0);

        #pragma unroll 1
        for (int ks = 0; ks < 3; ks++) {
            uint32_t a[4][4];
            #pragma unroll
            for (int mt = 0; mt < 4; mt++) {
                uint4 v = *(const uint4*)(smA + (((ks * 16) + warpM * 4 + mt) * 32 + lid) * 16);
                a[mt][0] = v.x; a[mt][1] = v.y; a[mt][2] = v.z; a[mt][3] = v.w;
            }
            uint32_t b[4][2];
            #pragma unroll
            for (int nt = 0; nt < 4; nt++) {
                const int pgrp = warpN * 4 + nt;
                uint2 v = *(const uint2*)(smB + (((ks * 8) + pgrp) * 32 + (lid ^ pgrp)) * 8);
                b[nt][0] = v.x; b[nt][1] = v.y;
            }
            #pragma unroll
            for (int mt = 0; mt < 4; mt++)
                #pragma unroll
                for (int nt = 0; nt < 4; nt++)
                    mma16816(acc[mt][nt], a[mt], b[nt]);
        }

        if (s < 15) bstore(s + 1, (uint32_t*)(sm + ((s & 1) ? OFF_B0 : OFF_B1)));
        if (s < 14) bload(s + 2);

        if (s < 15) {
            asm volatile("cp.async.wait_group 0;" ::: "memory");  // A(s+1) landed
            __syncthreads();
        }
    }

    // ---- epilogue: bn2 + relu, direct STG.64 ----
    #pragma unroll
    for (int mt = 0; mt < 4; mt++) {
        const int o0 = warpM * 64 + mt * 16 + (lid >> 2);
        const float a20 = sab2[2 * o0],       b20 = sab2[2 * o0 + 1];
        const float a21 = sab2[2 * (o0 + 8)], b21 = sab2[2 * (o0 + 8) + 1];
        float* orow0 = out + ((long)n * 256 + o0) * 500;
        float* orow1 = orow0 + 8 * 500;
        #pragma unroll
        for (int nt = 0; nt < 4; nt++) {
            const int pos = posbase + warpN * 32 + nt * 8 + (lid & 3) * 2;
            if (pos < 500) {
                float2 v0, v1;
                v0.x = fmaxf(fmaf(a20, acc[mt][nt][0], b20), 0.f);
                v0.y = fmaxf(fmaf(a20, acc[mt][nt][1], b20), 0.f);
                v1.x = fmaxf(fmaf(a21, acc[mt][nt][2], b21), 0.f);
                v1.y = fmaxf(fmaf(a21, acc[mt][nt][3], b21), 0.f);
                *(float2*)(orow0 + pos) = v0;
                *(float2*)(orow1 + pos) = v1;
            }
        }
    }
}

// ============================================================
extern "C" void kernel_launch(void* const* d_in, const int* in_sizes, int n_in,
                              void* d_out, int out_size) {
    const float* x    = (const float*)d_in[0];
    const float* Wg1  = (const float*)d_in[1];
    const float* Wg2  = (const float*)d_in[2];
    const float* Wl1  = (const float*)d_in[3];
    const float* Wl2  = (const float*)d_in[4];
    const float* Wc2  = (const float*)d_in[5];
    const float* bng  = (const float*)d_in[6];
    const float* bnl  = (const float*)d_in[7];
    const float* bn1p = (const float*)d_in[8];
    const float* bn2p = (const float*)d_in[9];
    float* out = (float*)d_out;

    static bool attr_set = false;
    if (!attr_set) {
        cudaFuncSetAttribute(k_main_mma, cudaFuncAttributeMaxDynamicSharedMemorySize, SMEM_TOT);
        cudaFuncSetAttribute(k_prep, cudaFuncAttributeMaxDynamicSharedMemorySize, SMEM_PREP);
        attr_set = true;
    }

    k_wprep<<<384, 256>>>(Wc2);
    k_prep<<<NBATCH, 512, SMEM_PREP>>>(x, Wg1, Wg2, Wl1, Wl2, bng, bnl);
    k_main_mma<<<dim3(8, NBATCH), 256, SMEM_TOT>>>(x, bn1p, bn2p, out);
}